// round 14
// baseline (speedup 1.0000x reference)
#include <cuda_runtime.h>
#include <cuda_fp16.h>
#include <cstdint>

#define N_NODES 12288
#define N_EDGES 6144
#define DIM     256

// ---------------- scratch (__device__ globals, allocation-free) ----------------
__device__ __align__(128) __half g_Hh [(size_t)N_NODES * N_EDGES]; // H fp16 (written by K2, read by K3)
__device__ __align__(128) __half g_xh [(size_t)N_NODES * DIM];     // x  fp16
__device__ __align__(128) __half g_Wh [(size_t)DIM * DIM];         // W  fp16
__device__ __align__(128) __half g_xnh [(size_t)N_NODES * DIM];    // xnorm fp16
__device__ __align__(128) __half g_xheh[(size_t)N_EDGES * DIM];    // xhe fp16
__device__ __align__(128) float  g_part[(size_t)3 * N_EDGES * DIM];// K2 split-K partials

// ---------------- helpers ----------------
__device__ __forceinline__ uint32_t smem_u32(const void* p) {
    uint32_t a;
    asm("{ .reg .u64 t; cvta.to.shared.u64 t, %1; cvt.u32.u64 %0, t; }" : "=r"(a) : "l"(p));
    return a;
}
__device__ __forceinline__ void cp16(uint32_t dst, const void* src) {
    asm volatile("cp.async.cg.shared.global [%0], [%1], 16;" :: "r"(dst), "l"(src) : "memory");
}
#define CP_COMMIT() asm volatile("cp.async.commit_group;" ::: "memory")
#define CP_WAIT1()  asm volatile("cp.async.wait_group 1;" ::: "memory")
#define CP_WAIT2()  asm volatile("cp.async.wait_group 2;" ::: "memory")

__device__ __forceinline__ void ldm_x4(uint32_t* r, uint32_t addr) {
    asm volatile("ldmatrix.sync.aligned.m8n8.x4.shared.b16 {%0,%1,%2,%3}, [%4];"
        : "=r"(r[0]), "=r"(r[1]), "=r"(r[2]), "=r"(r[3]) : "r"(addr));
}
__device__ __forceinline__ void ldm_x4t(uint32_t* r, uint32_t addr) {
    asm volatile("ldmatrix.sync.aligned.m8n8.x4.trans.shared.b16 {%0,%1,%2,%3}, [%4];"
        : "=r"(r[0]), "=r"(r[1]), "=r"(r[2]), "=r"(r[3]) : "r"(addr));
}
__device__ __forceinline__ void mma16816(float* c, const uint32_t* a, uint32_t b0, uint32_t b1) {
    asm volatile("mma.sync.aligned.m16n8k16.row.col.f32.f16.f16.f32 "
        "{%0,%1,%2,%3}, {%4,%5,%6,%7}, {%8,%9}, {%0,%1,%2,%3};"
        : "+f"(c[0]), "+f"(c[1]), "+f"(c[2]), "+f"(c[3])
        : "r"(a[0]), "r"(a[1]), "r"(a[2]), "r"(a[3]), "r"(b0), "r"(b1));
}

// ---------------- prep: fused x+W convert ----------------
__global__ __launch_bounds__(256) void convert_xw(const float4* __restrict__ x,
                                                  const float4* __restrict__ w,
                                                  __half2* __restrict__ xh,
                                                  __half2* __restrict__ wh) {
    const size_t i = (size_t)blockIdx.x * 256 + threadIdx.x;
    const size_t nx = (size_t)N_NODES * DIM / 4;
    if (i < nx) {
        const float4 v = x[i];
        xh[2 * i]     = __floats2half2_rn(v.x, v.y);
        xh[2 * i + 1] = __floats2half2_rn(v.z, v.w);
    } else {
        const size_t j = i - nx;
        const float4 v = w[j];
        wh[2 * j]     = __floats2half2_rn(v.x, v.y);
        wh[2 * j + 1] = __floats2half2_rn(v.z, v.w);
    }
}

// ================= K1: proven BK=32 / 4-stage / 8-warp fused GEMM =================
constexpr int PA1 = 80;
constexpr int PB1 = 128 * 2 + 16;
constexpr uint32_t A1_BYTES = 128 * PA1;
constexpr uint32_t B1_BYTES = 32 * PB1;
constexpr uint32_t STAGE1 = A1_BYTES + B1_BYTES;

__device__ __forceinline__ void load_stage_k1(
    uint32_t sb, const __half* __restrict__ A, const __half* __restrict__ B,
    size_t bm, size_t bn, size_t gk, int tid)
{
#pragma unroll
    for (int i = 0; i < 2; ++i) {
        const int c = tid + i * 256;
        const int r = c >> 2, u = c & 3;
        cp16(sb + (uint32_t)(r * PA1 + u * 16), A + (bm + r) * DIM + gk + u * 8);
    }
#pragma unroll
    for (int i = 0; i < 2; ++i) {
        const int c = tid + i * 256;
        const int r = c >> 4, u = c & 15;
        cp16(sb + A1_BYTES + (uint32_t)(r * PB1 + u * 16), B + (gk + r) * DIM + bn + u * 8);
    }
}

__global__ __launch_bounds__(256, 1) void gemm_k1(
    const __half* __restrict__ A, const __half* __restrict__ B,
    __half* __restrict__ outH, const float* __restrict__ bias,
    const float* __restrict__ scaleDiag, size_t sstride)
{
    extern __shared__ char smem[];
    const uint32_t smb = smem_u32(smem);
    const int tid = threadIdx.x;
    const int wid = tid >> 5, lane = tid & 31;
    const int wm = (wid >> 2) * 64;
    const int wn = (wid & 3) * 32;
    const size_t bm = (size_t)blockIdx.y * 128;
    const size_t bn = (size_t)blockIdx.x * 128;

    float acc[4][4][4];
#pragma unroll
    for (int m = 0; m < 4; ++m)
#pragma unroll
        for (int n = 0; n < 4; ++n)
#pragma unroll
            for (int q = 0; q < 4; ++q) acc[m][n][q] = 0.0f;

#pragma unroll
    for (int s = 0; s < 3; ++s) {
        load_stage_k1(smb + (uint32_t)s * STAGE1, A, B, bm, bn, (size_t)s * 32, tid);
        CP_COMMIT();
    }
    const int aRowF = lane & 15, aColF = (lane >> 4) << 3;
    const int bRow = lane & 15, bCol = (lane >> 4) << 3;

    for (int i = 0; i < 8; ++i) {
        CP_WAIT2();
        __syncthreads();
        if (i + 3 < 8) {
            load_stage_k1(smb + (uint32_t)((i + 3) & 3) * STAGE1, A, B, bm, bn,
                          (size_t)(i + 3) * 32, tid);
            CP_COMMIT();
        }
        const uint32_t sb = smb + (uint32_t)(i & 3) * STAGE1;
#pragma unroll
        for (int ks = 0; ks < 2; ++ks) {
            const int k0 = ks * 16;
            uint32_t ah[4][4], bh[2][4];
#pragma unroll
            for (int mt = 0; mt < 4; ++mt)
                ldm_x4(ah[mt], sb + (uint32_t)((wm + mt * 16 + aRowF) * PA1 + (k0 + aColF) * 2));
#pragma unroll
            for (int np = 0; np < 2; ++np)
                ldm_x4t(bh[np], sb + A1_BYTES +
                        (uint32_t)((k0 + bRow) * PB1 + (wn + np * 16 + bCol) * 2));
#pragma unroll
            for (int mt = 0; mt < 4; ++mt)
#pragma unroll
                for (int nf = 0; nf < 4; ++nf) {
                    const int bi = nf >> 1, o = (nf & 1) * 2;
                    mma16816(acc[mt][nf], ah[mt], bh[bi][o], bh[bi][o + 1]);
                }
        }
    }

    const int gq = lane >> 2, tc = (lane & 3) * 2;
#pragma unroll
    for (int mt = 0; mt < 4; ++mt) {
        const size_t r0 = bm + wm + mt * 16 + gq;
        const float s0 = scaleDiag[r0 * sstride];
        const float s1 = scaleDiag[(r0 + 8) * sstride];
#pragma unroll
        for (int nf = 0; nf < 4; ++nf) {
            const size_t c0 = bn + wn + nf * 8 + tc;
            const float b0 = bias[c0], b1 = bias[c0 + 1];
            *reinterpret_cast<__half2*>(&outH[r0 * DIM + c0]) =
                __floats2half2_rn((acc[mt][nf][0] + b0) * s0, (acc[mt][nf][1] + b1) * s0);
            *reinterpret_cast<__half2*>(&outH[(r0 + 8) * DIM + c0]) =
                __floats2half2_rn((acc[mt][nf][2] + b0) * s1, (acc[mt][nf][3] + b1) * s1);
        }
    }
}

// ============ big-GEMM common constants ============
constexpr int BK = 64;
constexpr int PA_F = BK * 2 + 16;          // 144
constexpr int PA_T = 272;
constexpr int PB   = 128 * 2 + 16;         // 272
constexpr uint32_t BB = BK * PB;           // 17408

// ================= K2: trans-A GEMM with FUSED fp32->fp16 H conversion =================
// A tiles: LDG.128 fp32 H -> cvt -> st.shared (swizzled stage) ; x==0 panel also STGs g_Hh.
// B: 3-stage cp.async ring (unchanged). Single-buffered fragments (register budget).
__global__ __launch_bounds__(256, 2) void mma_gemm_k2(
    const float* __restrict__ H32, __half* __restrict__ Hh,
    const __half* __restrict__ B,
    int kLen, float* __restrict__ outF, size_t outPlane)
{
    constexpr uint32_t ABYTES = (uint32_t)(BK * PA_T);   // 17408
    constexpr uint32_t STAGE  = ABYTES + BB;             // 34816
    const size_t lda = (size_t)N_EDGES;

    extern __shared__ char smem[];
    const uint32_t smb = smem_u32(smem);
    const int tid = threadIdx.x;
    const int wid = tid >> 5, lane = tid & 31;
    const int wm = (wid >> 2) * 64;
    const int wn = (wid & 3) * 32;
    const size_t bm = (size_t)blockIdx.y * 128;       // E offset (GEMM M)
    const size_t bn = (size_t)blockIdx.x * 128;       // DIM panel
    const size_t gk0 = (size_t)blockIdx.z * kLen;     // N offset (GEMM K)
    const int nchunks = kLen / BK;                    // 64
    const bool doStg = (blockIdx.x == 0);

    float acc[4][4][4];
#pragma unroll
    for (int m = 0; m < 4; ++m)
#pragma unroll
        for (int n = 0; n < 4; ++n)
#pragma unroll
            for (int q = 0; q < 4; ++q) acc[m][n][q] = 0.0f;

    uint32_t h2[16];   // one converted A chunk (per-thread slice)

    // LDG fp32 + convert one A chunk into h2
    auto ldg_cvt = [&](size_t gk) {
#pragma unroll
        for (int p = 0; p < 4; ++p) {
            const int c = tid + (p << 8);
            const int r = c >> 4, u = c & 15;
            const float4* s = reinterpret_cast<const float4*>(
                H32 + (gk + r) * lda + bm + (size_t)u * 8);
            const float4 a = s[0], b = s[1];
            __half2 q0 = __floats2half2_rn(a.x, a.y), q1 = __floats2half2_rn(a.z, a.w);
            __half2 q2 = __floats2half2_rn(b.x, b.y), q3 = __floats2half2_rn(b.z, b.w);
            h2[p * 4 + 0] = *reinterpret_cast<uint32_t*>(&q0);
            h2[p * 4 + 1] = *reinterpret_cast<uint32_t*>(&q1);
            h2[p * 4 + 2] = *reinterpret_cast<uint32_t*>(&q2);
            h2[p * 4 + 3] = *reinterpret_cast<uint32_t*>(&q3);
        }
    };
    // STS h2 into stage (swizzle layout identical to old cp16 path) + optional STG to g_Hh
    auto sts_stg = [&](uint32_t sbA, size_t gk) {
#pragma unroll
        for (int p = 0; p < 4; ++p) {
            const int c = tid + (p << 8);
            const int r = c >> 4, u = c & 15;
            asm volatile("st.shared.v4.b32 [%0], {%1,%2,%3,%4};"
                :: "r"(sbA + (uint32_t)(r * PA_T + u * 16)),
                   "r"(h2[p * 4 + 0]), "r"(h2[p * 4 + 1]),
                   "r"(h2[p * 4 + 2]), "r"(h2[p * 4 + 3]) : "memory");
            if (doStg) {
                *reinterpret_cast<uint4*>(Hh + (gk + r) * lda + bm + (size_t)u * 8) =
                    make_uint4(h2[p * 4 + 0], h2[p * 4 + 1], h2[p * 4 + 2], h2[p * 4 + 3]);
            }
        }
    };
    auto loadB = [&](uint32_t sbase, size_t gk) {
#pragma unroll
        for (int i = 0; i < 4; ++i) {
            const int c = tid + i * 256;
            const int r = c >> 4, u = c & 15;
            cp16(sbase + ABYTES + (uint32_t)(r * PB + u * 16),
                 B + (gk + r) * DIM + bn + u * 8);
        }
    };

    // prologue: A chunks 0,1 -> smem ; B chunks 0,1 via cp.async ; A chunk 2 -> regs
    ldg_cvt(gk0);            sts_stg(smb, gk0);
    ldg_cvt(gk0 + BK);       sts_stg(smb + STAGE, gk0 + BK);
    loadB(smb, gk0);                 CP_COMMIT();
    loadB(smb + STAGE, gk0 + BK);    CP_COMMIT();
    ldg_cvt(gk0 + 2 * BK);

    const int aRowT = (lane & 7) + ((lane >> 4) << 3);
    const int aColT = ((lane >> 3) & 1) << 3;
    const int bRow = lane & 15;
    const int bCol = (lane >> 4) << 3;

    int stage = 0;
    for (int i = 0; i < nchunks; ++i) {
        CP_WAIT1();
        __syncthreads();

        const uint32_t sb = smb + (uint32_t)stage * STAGE;
        if (i + 2 < nchunks) {
            const int ps = (stage + 2 >= 3) ? stage - 1 : stage + 2;
            const size_t gk = gk0 + (size_t)(i + 2) * BK;
            sts_stg(smb + (uint32_t)ps * STAGE, gk);   // A(i+2) regs -> smem (+Hh)
            loadB(smb + (uint32_t)ps * STAGE, gk);
            CP_COMMIT();
        }
        if (i + 3 < nchunks) ldg_cvt(gk0 + (size_t)(i + 3) * BK);  // A(i+3) -> regs

#pragma unroll
        for (int ks = 0; ks < 4; ++ks) {
            const int k0 = ks * 16;
            uint32_t ah[4][4], bh[2][4];
#pragma unroll
            for (int mt = 0; mt < 4; ++mt)
                ldm_x4t(ah[mt], sb +
                    (uint32_t)((k0 + aRowT) * PA_T + (wm + mt * 16 + aColT) * 2));
#pragma unroll
            for (int np = 0; np < 2; ++np)
                ldm_x4t(bh[np], sb + ABYTES +
                        (uint32_t)((k0 + bRow) * PB + (wn + np * 16 + bCol) * 2));
#pragma unroll
            for (int mt = 0; mt < 4; ++mt)
#pragma unroll
                for (int nf = 0; nf < 4; ++nf) {
                    const int bi = nf >> 1, o = (nf & 1) * 2;
                    mma16816(acc[mt][nf], ah[mt], bh[bi][o], bh[bi][o + 1]);
                }
        }
        stage = (stage + 1 == 3) ? 0 : stage + 1;
    }

    float* out = outF + (size_t)blockIdx.z * outPlane;
    const int gq = lane >> 2, tc = (lane & 3) * 2;
#pragma unroll
    for (int mt = 0; mt < 4; ++mt) {
#pragma unroll
        for (int nf = 0; nf < 4; ++nf) {
            const size_t r0 = bm + wm + mt * 16 + gq;
            const size_t c0 = bn + wn + nf * 8 + tc;
            *reinterpret_cast<float2*>(&out[r0 * DIM + c0]) =
                make_float2(acc[mt][nf][0], acc[mt][nf][1]);
            *reinterpret_cast<float2*>(&out[(r0 + 8) * DIM + c0]) =
                make_float2(acc[mt][nf][2], acc[mt][nf][3]);
        }
    }
}

// ============ K3: 128x128 tile, BK=64, 3 stages, frag double-buffer, atomic epilogue ============
__device__ __forceinline__ void load_stage_k3(
    uint32_t sb, const __half* __restrict__ A, const __half* __restrict__ B,
    size_t bm, size_t lda, size_t bn, size_t gk, int tid)
{
#pragma unroll
    for (int i = 0; i < 4; ++i) {
        const int c = tid + i * 256;
        const int r = c >> 3, u = c & 7;
        cp16(sb + (uint32_t)(r * PA_F + u * 16), A + (bm + r) * lda + gk + u * 8);
    }
#pragma unroll
    for (int i = 0; i < 4; ++i) {
        const int c = tid + i * 256;
        const int r = c >> 4, u = c & 15;
        cp16(sb + (uint32_t)(128 * PA_F) + (uint32_t)(r * PB + u * 16),
             B + (gk + r) * DIM + bn + u * 8);
    }
}

__global__ __launch_bounds__(256, 2) void mma_gemm_k3(
    const __half* __restrict__ A, size_t lda,
    const __half* __restrict__ B,
    int kLen, float* __restrict__ outF,
    const float* __restrict__ scaleDiag, size_t sstride)
{
    constexpr uint32_t ABYTES = (uint32_t)(128 * PA_F);
    constexpr uint32_t STAGE  = ABYTES + BB;

    extern __shared__ char smem[];
    const uint32_t smb = smem_u32(smem);
    const int tid = threadIdx.x;
    const int wid = tid >> 5, lane = tid & 31;
    const int wm = (wid >> 2) * 64;
    const int wn = (wid & 3) * 32;
    const size_t bm = (size_t)blockIdx.y * 128;
    const size_t bn = (size_t)blockIdx.x * 128;
    const size_t gk0 = (size_t)blockIdx.z * kLen;
    const int nchunks = kLen / BK;

    float acc[4][4][4];
#pragma unroll
    for (int m = 0; m < 4; ++m)
#pragma unroll
        for (int n = 0; n < 4; ++n)
#pragma unroll
            for (int q = 0; q < 4; ++q) acc[m][n][q] = 0.0f;

#pragma unroll
    for (int s = 0; s < 2; ++s) {
        load_stage_k3(smb + (uint32_t)s * STAGE, A, B, bm, lda, bn,
                      gk0 + (size_t)s * BK, tid);
        CP_COMMIT();
    }

    const int aRowF = lane & 15;
    const int aColF = (lane >> 4) << 3;
    const int bRow = lane & 15;
    const int bCol = (lane >> 4) << 3;

    uint32_t ah[2][4][4], bh[2][2][4];
    auto load_frags = [&](uint32_t sb, int ks, int buf) {
        const int k0 = ks * 16;
#pragma unroll
        for (int mt = 0; mt < 4; ++mt)
            ldm_x4(ah[buf][mt], sb +
                (uint32_t)((wm + mt * 16 + aRowF) * PA_F + (k0 + aColF) * 2));
#pragma unroll
        for (int np = 0; np < 2; ++np)
            ldm_x4t(bh[buf][np], sb + ABYTES +
                    (uint32_t)((k0 + bRow) * PB + (wn + np * 16 + bCol) * 2));
    };

    int stage = 0;
    for (int i = 0; i < nchunks; ++i) {
        CP_WAIT1();
        __syncthreads();

        const uint32_t sb = smb + (uint32_t)stage * STAGE;
        load_frags(sb, 0, 0);

        if (i + 2 < nchunks) {
            const int ps = (stage + 2 >= 3) ? stage - 1 : stage + 2;
            load_stage_k3(smb + (uint32_t)ps * STAGE, A, B, bm, lda, bn,
                          gk0 + (size_t)(i + 2) * BK, tid);
            CP_COMMIT();
        }

#pragma unroll
        for (int ks = 0; ks < 4; ++ks) {
            const int cur = ks & 1;
            if (ks < 3) load_frags(sb, ks + 1, cur ^ 1);
#pragma unroll
            for (int mt = 0; mt < 4; ++mt)
#pragma unroll
                for (int nf = 0; nf < 4; ++nf) {
                    const int bi = nf >> 1, o = (nf & 1) * 2;
                    mma16816(acc[mt][nf], ah[cur][mt], bh[cur][bi][o], bh[cur][bi][o + 1]);
                }
        }
        stage = (stage + 1 == 3) ? 0 : stage + 1;
    }

    const int gq = lane >> 2, tc = (lane & 3) * 2;
#pragma unroll
    for (int mt = 0; mt < 4; ++mt) {
        const size_t r0 = bm + wm + mt * 16 + gq;
        const float s0 = scaleDiag[r0 * sstride];
        const float s1 = scaleDiag[(r0 + 8) * sstride];
#pragma unroll
        for (int nf = 0; nf < 4; ++nf) {
            const size_t c0 = bn + wn + nf * 8 + tc;
            atomicAdd(&outF[r0 * DIM + c0],           acc[mt][nf][0] * s0);
            atomicAdd(&outF[r0 * DIM + c0 + 1],       acc[mt][nf][1] * s0);
            atomicAdd(&outF[(r0 + 8) * DIM + c0],     acc[mt][nf][2] * s1);
            atomicAdd(&outF[(r0 + 8) * DIM + c0 + 1], acc[mt][nf][3] * s1);
        }
    }
}

// ---------------- reduce for K2 (float4) ----------------
__global__ __launch_bounds__(256) void reduce_k2(const float* __restrict__ De) {
    const size_t i4 = (size_t)blockIdx.x * 256 + threadIdx.x;
    const size_t e = (i4 * 4) >> 8;
    const float4* p0 = (const float4*)g_part;
    const float4 a = p0[i4];
    const float4 b = p0[(size_t)N_EDGES * DIM / 4 + i4];
    const float4 c = p0[(size_t)2 * N_EDGES * DIM / 4 + i4];
    const float sc = De[e * (N_EDGES + 1)];
    __half2 h0 = __floats2half2_rn((a.x + b.x + c.x) * sc, (a.y + b.y + c.y) * sc);
    __half2 h1 = __floats2half2_rn((a.z + b.z + c.z) * sc, (a.w + b.w + c.w) * sc);
    *reinterpret_cast<__half2*>(&g_xheh[i4 * 4])     = h0;
    *reinterpret_cast<__half2*>(&g_xheh[i4 * 4 + 2]) = h1;
}

// ---------------- launch ----------------
extern "C" void kernel_launch(void* const* d_in, const int* in_sizes, int n_in,
                              void* d_out, int out_size)
{
    const float* x  = (const float*)d_in[0];
    const float* H  = (const float*)d_in[1];
    const float* Dv = (const float*)d_in[2];
    const float* De = (const float*)d_in[3];
    const float* W  = (const float*)d_in[4];
    const float* b  = (const float*)d_in[5];
    float* out = (float*)d_out;

    __half *Hh, *xh, *Wh, *xnh, *xheh;
    float* part;
    cudaGetSymbolAddress((void**)&Hh, g_Hh);
    cudaGetSymbolAddress((void**)&xh, g_xh);
    cudaGetSymbolAddress((void**)&Wh, g_Wh);
    cudaGetSymbolAddress((void**)&xnh, g_xnh);
    cudaGetSymbolAddress((void**)&xheh, g_xheh);
    cudaGetSymbolAddress((void**)&part, g_part);

    constexpr uint32_t SMEM_K1 = 4 * STAGE1;
    constexpr uint32_t SMEM_K2 = 3 * ((uint32_t)(BK * PA_T) + BB);   // 104448
    constexpr uint32_t SMEM_K3 = 3 * ((uint32_t)(128 * PA_F) + BB);  // 107520
    cudaFuncSetAttribute((const void*)gemm_k1,
                         cudaFuncAttributeMaxDynamicSharedMemorySize, SMEM_K1);
    cudaFuncSetAttribute((const void*)mma_gemm_k2,
                         cudaFuncAttributeMaxDynamicSharedMemorySize, SMEM_K2);
    cudaFuncSetAttribute((const void*)mma_gemm_k3,
                         cudaFuncAttributeMaxDynamicSharedMemorySize, SMEM_K3);

    // 1) fused x+W convert
    {
        const size_t nx = (size_t)N_NODES * DIM / 4;
        const size_t nw = (size_t)DIM * DIM / 4;
        convert_xw<<<(unsigned)((nx + nw) / 256), 256>>>(
            (const float4*)x, (const float4*)W, (__half2*)xh, (__half2*)Wh);
    }

    // zero d_out for K3's atomic epilogue
    cudaMemsetAsync(out, 0, (size_t)N_NODES * DIM * sizeof(float), 0);

    // 2) K1 (fused bias + dv-scale -> fp16 xnorm)
    gemm_k1<<<dim3(2, N_NODES / 128, 1), 256, SMEM_K1>>>(
        xh, Wh, xnh, b, Dv, (size_t)N_NODES + 1);

    // 3) K2: H^T @ xnorm with fused fp32->fp16 H conversion (writes g_Hh for K3)
    mma_gemm_k2<<<dim3(2, N_EDGES / 128, 3), 256, SMEM_K2>>>(
        H, Hh, xnh, N_NODES / 3, part, (size_t)N_EDGES * DIM);

    // 4) reduce + de-scale -> xhe fp16
    reduce_k2<<<(N_EDGES * DIM / 4) / 256, 256>>>(De);

    // 5) K3: H @ xhe, split-K=3, fused dv-scale atomic epilogue -> out
    mma_gemm_k3<<<dim3(2, N_NODES / 128, 3), 256, SMEM_K3>>>(
        Hh, (size_t)N_EDGES, xheh, N_EDGES / 3, out,
        Dv, (size_t)N_NODES + 1);
}

// round 15
// speedup vs baseline: 1.0390x; 1.0390x over previous
#include <cuda_runtime.h>
#include <cuda_fp16.h>
#include <cstdint>

#define N_NODES 12288
#define N_EDGES 6144
#define DIM     256
#define K2_SPLIT 6
#define K2_LEN  (N_NODES / K2_SPLIT)   // 2048

// ---------------- scratch (__device__ globals, allocation-free) ----------------
__device__ __align__(128) __half g_Hh [(size_t)N_NODES * N_EDGES];
__device__ __align__(128) __half g_xh [(size_t)N_NODES * DIM];
__device__ __align__(128) __half g_Wh [(size_t)DIM * DIM];
__device__ __align__(128) __half g_xnh [(size_t)N_NODES * DIM];
__device__ __align__(128) __half g_xheh[(size_t)N_EDGES * DIM];
__device__ __align__(128) float  g_part[(size_t)K2_SPLIT * N_EDGES * DIM];

// ---------------- helpers ----------------
__device__ __forceinline__ uint32_t smem_u32(const void* p) {
    uint32_t a;
    asm("{ .reg .u64 t; cvta.to.shared.u64 t, %1; cvt.u32.u64 %0, t; }" : "=r"(a) : "l"(p));
    return a;
}
__device__ __forceinline__ void cp16(uint32_t dst, const void* src) {
    asm volatile("cp.async.cg.shared.global [%0], [%1], 16;" :: "r"(dst), "l"(src) : "memory");
}
#define CP_COMMIT() asm volatile("cp.async.commit_group;" ::: "memory")
#define CP_WAIT1()  asm volatile("cp.async.wait_group 1;" ::: "memory")
#define CP_WAIT2()  asm volatile("cp.async.wait_group 2;" ::: "memory")

__device__ __forceinline__ void ldm_x4(uint32_t* r, uint32_t addr) {
    asm volatile("ldmatrix.sync.aligned.m8n8.x4.shared.b16 {%0,%1,%2,%3}, [%4];"
        : "=r"(r[0]), "=r"(r[1]), "=r"(r[2]), "=r"(r[3]) : "r"(addr));
}
__device__ __forceinline__ void ldm_x4t(uint32_t* r, uint32_t addr) {
    asm volatile("ldmatrix.sync.aligned.m8n8.x4.trans.shared.b16 {%0,%1,%2,%3}, [%4];"
        : "=r"(r[0]), "=r"(r[1]), "=r"(r[2]), "=r"(r[3]) : "r"(addr));
}
__device__ __forceinline__ void mma16816(float* c, const uint32_t* a, uint32_t b0, uint32_t b1) {
    asm volatile("mma.sync.aligned.m16n8k16.row.col.f32.f16.f16.f32 "
        "{%0,%1,%2,%3}, {%4,%5,%6,%7}, {%8,%9}, {%0,%1,%2,%3};"
        : "+f"(c[0]), "+f"(c[1]), "+f"(c[2]), "+f"(c[3])
        : "r"(a[0]), "r"(a[1]), "r"(a[2]), "r"(a[3]), "r"(b0), "r"(b1));
}

// ---------------- prep converts ----------------
__global__ __launch_bounds__(256) void convert_H8(const float4* __restrict__ in,
                                                  uint4* __restrict__ out) {
    const size_t i = (size_t)blockIdx.x * 256 + threadIdx.x;
    const float4 a = in[2 * i];
    const float4 b = in[2 * i + 1];
    __half2 h0 = __floats2half2_rn(a.x, a.y), h1 = __floats2half2_rn(a.z, a.w);
    __half2 h2 = __floats2half2_rn(b.x, b.y), h3 = __floats2half2_rn(b.z, b.w);
    uint4 v;
    v.x = *reinterpret_cast<uint32_t*>(&h0);
    v.y = *reinterpret_cast<uint32_t*>(&h1);
    v.z = *reinterpret_cast<uint32_t*>(&h2);
    v.w = *reinterpret_cast<uint32_t*>(&h3);
    out[i] = v;
}

__global__ __launch_bounds__(256) void convert_xw(const float4* __restrict__ x,
                                                  const float4* __restrict__ w,
                                                  __half2* __restrict__ xh,
                                                  __half2* __restrict__ wh) {
    const size_t i = (size_t)blockIdx.x * 256 + threadIdx.x;
    const size_t nx = (size_t)N_NODES * DIM / 4;
    if (i < nx) {
        const float4 v = x[i];
        xh[2 * i]     = __floats2half2_rn(v.x, v.y);
        xh[2 * i + 1] = __floats2half2_rn(v.z, v.w);
    } else {
        const size_t j = i - nx;
        const float4 v = w[j];
        wh[2 * j]     = __floats2half2_rn(v.x, v.y);
        wh[2 * j + 1] = __floats2half2_rn(v.z, v.w);
    }
}

// ================= K1: proven BK=32 / 4-stage / 8-warp fused GEMM =================
constexpr int PA1 = 80;
constexpr int PB1 = 128 * 2 + 16;
constexpr uint32_t A1_BYTES = 128 * PA1;
constexpr uint32_t B1_BYTES = 32 * PB1;
constexpr uint32_t STAGE1 = A1_BYTES + B1_BYTES;

__device__ __forceinline__ void load_stage_k1(
    uint32_t sb, const __half* __restrict__ A, const __half* __restrict__ B,
    size_t bm, size_t bn, size_t gk, int tid)
{
#pragma unroll
    for (int i = 0; i < 2; ++i) {
        const int c = tid + i * 256;
        const int r = c >> 2, u = c & 3;
        cp16(sb + (uint32_t)(r * PA1 + u * 16), A + (bm + r) * DIM + gk + u * 8);
    }
#pragma unroll
    for (int i = 0; i < 2; ++i) {
        const int c = tid + i * 256;
        const int r = c >> 4, u = c & 15;
        cp16(sb + A1_BYTES + (uint32_t)(r * PB1 + u * 16), B + (gk + r) * DIM + bn + u * 8);
    }
}

__global__ __launch_bounds__(256, 1) void gemm_k1(
    const __half* __restrict__ A, const __half* __restrict__ B,
    __half* __restrict__ outH, const float* __restrict__ bias,
    const float* __restrict__ scaleDiag, size_t sstride)
{
    extern __shared__ char smem[];
    const uint32_t smb = smem_u32(smem);
    const int tid = threadIdx.x;
    const int wid = tid >> 5, lane = tid & 31;
    const int wm = (wid >> 2) * 64;
    const int wn = (wid & 3) * 32;
    const size_t bm = (size_t)blockIdx.y * 128;
    const size_t bn = (size_t)blockIdx.x * 128;

    float acc[4][4][4];
#pragma unroll
    for (int m = 0; m < 4; ++m)
#pragma unroll
        for (int n = 0; n < 4; ++n)
#pragma unroll
            for (int q = 0; q < 4; ++q) acc[m][n][q] = 0.0f;

#pragma unroll
    for (int s = 0; s < 3; ++s) {
        load_stage_k1(smb + (uint32_t)s * STAGE1, A, B, bm, bn, (size_t)s * 32, tid);
        CP_COMMIT();
    }
    const int aRowF = lane & 15, aColF = (lane >> 4) << 3;
    const int bRow = lane & 15, bCol = (lane >> 4) << 3;

    for (int i = 0; i < 8; ++i) {
        CP_WAIT2();
        __syncthreads();
        if (i + 3 < 8) {
            load_stage_k1(smb + (uint32_t)((i + 3) & 3) * STAGE1, A, B, bm, bn,
                          (size_t)(i + 3) * 32, tid);
            CP_COMMIT();
        }
        const uint32_t sb = smb + (uint32_t)(i & 3) * STAGE1;
#pragma unroll
        for (int ks = 0; ks < 2; ++ks) {
            const int k0 = ks * 16;
            uint32_t ah[4][4], bh[2][4];
#pragma unroll
            for (int mt = 0; mt < 4; ++mt)
                ldm_x4(ah[mt], sb + (uint32_t)((wm + mt * 16 + aRowF) * PA1 + (k0 + aColF) * 2));
#pragma unroll
            for (int np = 0; np < 2; ++np)
                ldm_x4t(bh[np], sb + A1_BYTES +
                        (uint32_t)((k0 + bRow) * PB1 + (wn + np * 16 + bCol) * 2));
#pragma unroll
            for (int mt = 0; mt < 4; ++mt)
#pragma unroll
                for (int nf = 0; nf < 4; ++nf) {
                    const int bi = nf >> 1, o = (nf & 1) * 2;
                    mma16816(acc[mt][nf], ah[mt], bh[bi][o], bh[bi][o + 1]);
                }
        }
    }

    const int gq = lane >> 2, tc = (lane & 3) * 2;
#pragma unroll
    for (int mt = 0; mt < 4; ++mt) {
        const size_t r0 = bm + wm + mt * 16 + gq;
        const float s0 = scaleDiag[r0 * sstride];
        const float s1 = scaleDiag[(r0 + 8) * sstride];
#pragma unroll
        for (int nf = 0; nf < 4; ++nf) {
            const size_t c0 = bn + wn + nf * 8 + tc;
            const float b0 = bias[c0], b1 = bias[c0 + 1];
            *reinterpret_cast<__half2*>(&outH[r0 * DIM + c0]) =
                __floats2half2_rn((acc[mt][nf][0] + b0) * s0, (acc[mt][nf][1] + b1) * s0);
            *reinterpret_cast<__half2*>(&outH[(r0 + 8) * DIM + c0]) =
                __floats2half2_rn((acc[mt][nf][2] + b0) * s1, (acc[mt][nf][3] + b1) * s1);
        }
    }
}

// ============ big GEMM (R13-proven): 128x128, BK=64, 3 stages, frag dbl-buffer, 2 CTA/SM ========
constexpr int BK = 64;
constexpr int PA_F = BK * 2 + 16;          // 144
constexpr int PA_T = 272;
constexpr int PB   = 128 * 2 + 16;         // 272
constexpr uint32_t BB = BK * PB;           // 17408

template<bool TRANSA>
__device__ __forceinline__ void load_stage(
    uint32_t sb, uint32_t aBytes,
    const __half* __restrict__ A, const __half* __restrict__ B,
    size_t bm, size_t lda, size_t bn, size_t gk, int tid)
{
    if (TRANSA) {
#pragma unroll
        for (int i = 0; i < 4; ++i) {
            const int c = tid + i * 256;
            const int r = c >> 4, u = c & 15;
            cp16(sb + (uint32_t)(r * PA_T + u * 16), A + (gk + r) * lda + bm + u * 8);
        }
    } else {
#pragma unroll
        for (int i = 0; i < 4; ++i) {
            const int c = tid + i * 256;
            const int r = c >> 3, u = c & 7;
            cp16(sb + (uint32_t)(r * PA_F + u * 16), A + (bm + r) * lda + gk + u * 8);
        }
    }
#pragma unroll
    for (int i = 0; i < 4; ++i) {
        const int c = tid + i * 256;
        const int r = c >> 4, u = c & 15;
        cp16(sb + aBytes + (uint32_t)(r * PB + u * 16), B + (gk + r) * DIM + bn + u * 8);
    }
}

// ATOMIC=false (K2): zIdx passed explicitly (z launched separately); writes fp32 partial plane.
// ATOMIC=true  (K3): z from blockIdx.z; atomicAdd(out, scale[r]*acc).
template<bool TRANSA, bool ATOMIC>
__global__ __launch_bounds__(256, 2) void mma_gemm(
    const __half* __restrict__ A, size_t lda,
    const __half* __restrict__ B,
    int kLen, int zIdx, float* __restrict__ outF, size_t outPlane,
    const float* __restrict__ scaleDiag, size_t sstride)
{
    constexpr uint32_t ABYTES = TRANSA ? (uint32_t)(BK * PA_T) : (uint32_t)(128 * PA_F);
    constexpr uint32_t STAGE  = ABYTES + BB;

    extern __shared__ char smem[];
    const uint32_t smb = smem_u32(smem);
    const int tid = threadIdx.x;
    const int wid = tid >> 5, lane = tid & 31;
    const int wm = (wid >> 2) * 64;
    const int wn = (wid & 3) * 32;
    const size_t bm = (size_t)blockIdx.y * 128;
    const size_t bn = (size_t)blockIdx.x * 128;
    const int zz = ATOMIC ? (int)blockIdx.z : zIdx;
    const size_t gk0 = (size_t)zz * kLen;
    const int nchunks = kLen / BK;

    float acc[4][4][4];
#pragma unroll
    for (int m = 0; m < 4; ++m)
#pragma unroll
        for (int n = 0; n < 4; ++n)
#pragma unroll
            for (int q = 0; q < 4; ++q) acc[m][n][q] = 0.0f;

#pragma unroll
    for (int s = 0; s < 2; ++s) {
        load_stage<TRANSA>(smb + (uint32_t)s * STAGE, ABYTES, A, B,
                           bm, lda, bn, gk0 + (size_t)s * BK, tid);
        CP_COMMIT();
    }

    const int aRowF = lane & 15;
    const int aColF = (lane >> 4) << 3;
    const int aRowT = (lane & 7) + ((lane >> 4) << 3);
    const int aColT = ((lane >> 3) & 1) << 3;
    const int bRow = lane & 15;
    const int bCol = (lane >> 4) << 3;

    uint32_t ah[2][4][4], bh[2][2][4];
    auto load_frags = [&](uint32_t sb, int ks, int buf) {
        const int k0 = ks * 16;
#pragma unroll
        for (int mt = 0; mt < 4; ++mt) {
            if (TRANSA) {
                ldm_x4t(ah[buf][mt], sb +
                    (uint32_t)((k0 + aRowT) * PA_T + (wm + mt * 16 + aColT) * 2));
            } else {
                ldm_x4(ah[buf][mt], sb +
                    (uint32_t)((wm + mt * 16 + aRowF) * PA_F + (k0 + aColF) * 2));
            }
        }
#pragma unroll
        for (int np = 0; np < 2; ++np)
            ldm_x4t(bh[buf][np], sb + ABYTES +
                    (uint32_t)((k0 + bRow) * PB + (wn + np * 16 + bCol) * 2));
    };

    int stage = 0;
    for (int i = 0; i < nchunks; ++i) {
        CP_WAIT1();
        __syncthreads();

        const uint32_t sb = smb + (uint32_t)stage * STAGE;
        load_frags(sb, 0, 0);

        if (i + 2 < nchunks) {
            const int ps = (stage + 2 >= 3) ? stage - 1 : stage + 2;
            load_stage<TRANSA>(smb + (uint32_t)ps * STAGE, ABYTES, A, B,
                               bm, lda, bn, gk0 + (size_t)(i + 2) * BK, tid);
            CP_COMMIT();
        }

#pragma unroll
        for (int ks = 0; ks < 4; ++ks) {
            const int cur = ks & 1;
            if (ks < 3) load_frags(sb, ks + 1, cur ^ 1);
#pragma unroll
            for (int mt = 0; mt < 4; ++mt)
#pragma unroll
                for (int nf = 0; nf < 4; ++nf) {
                    const int bi = nf >> 1, o = (nf & 1) * 2;
                    mma16816(acc[mt][nf], ah[cur][mt], bh[cur][bi][o], bh[cur][bi][o + 1]);
                }
        }
        stage = (stage + 1 == 3) ? 0 : stage + 1;
    }

    const int gq = lane >> 2, tc = (lane & 3) * 2;
    if (ATOMIC) {
#pragma unroll
        for (int mt = 0; mt < 4; ++mt) {
            const size_t r0 = bm + wm + mt * 16 + gq;
            const float s0 = scaleDiag[r0 * sstride];
            const float s1 = scaleDiag[(r0 + 8) * sstride];
#pragma unroll
            for (int nf = 0; nf < 4; ++nf) {
                const size_t c0 = bn + wn + nf * 8 + tc;
                atomicAdd(&outF[r0 * DIM + c0],           acc[mt][nf][0] * s0);
                atomicAdd(&outF[r0 * DIM + c0 + 1],       acc[mt][nf][1] * s0);
                atomicAdd(&outF[(r0 + 8) * DIM + c0],     acc[mt][nf][2] * s1);
                atomicAdd(&outF[(r0 + 8) * DIM + c0 + 1], acc[mt][nf][3] * s1);
            }
        }
    } else {
        float* out = outF + (size_t)zz * outPlane;
#pragma unroll
        for (int mt = 0; mt < 4; ++mt) {
#pragma unroll
            for (int nf = 0; nf < 4; ++nf) {
                const size_t r0 = bm + wm + mt * 16 + gq;
                const size_t c0 = bn + wn + nf * 8 + tc;
                *reinterpret_cast<float2*>(&out[r0 * DIM + c0]) =
                    make_float2(acc[mt][nf][0], acc[mt][nf][1]);
                *reinterpret_cast<float2*>(&out[(r0 + 8) * DIM + c0]) =
                    make_float2(acc[mt][nf][2], acc[mt][nf][3]);
            }
        }
    }
}

// ---------------- reduce for K2 (float4, 6 planes) ----------------
__global__ __launch_bounds__(256) void reduce_k2(const float* __restrict__ De) {
    const size_t i4 = (size_t)blockIdx.x * 256 + threadIdx.x;
    const size_t e = (i4 * 4) >> 8;
    const float4* p0 = (const float4*)g_part;
    const size_t plane = (size_t)N_EDGES * DIM / 4;
    float4 s = p0[i4];
#pragma unroll
    for (int z = 1; z < K2_SPLIT; ++z) {
        const float4 v = p0[(size_t)z * plane + i4];
        s.x += v.x; s.y += v.y; s.z += v.z; s.w += v.w;
    }
    const float sc = De[e * (N_EDGES + 1)];
    __half2 h0 = __floats2half2_rn(s.x * sc, s.y * sc);
    __half2 h1 = __floats2half2_rn(s.z * sc, s.w * sc);
    *reinterpret_cast<__half2*>(&g_xheh[i4 * 4])     = h0;
    *reinterpret_cast<__half2*>(&g_xheh[i4 * 4 + 2]) = h1;
}

// ---------------- launch ----------------
extern "C" void kernel_launch(void* const* d_in, const int* in_sizes, int n_in,
                              void* d_out, int out_size)
{
    const float* x  = (const float*)d_in[0];
    const float* H  = (const float*)d_in[1];
    const float* Dv = (const float*)d_in[2];
    const float* De = (const float*)d_in[3];
    const float* W  = (const float*)d_in[4];
    const float* b  = (const float*)d_in[5];
    float* out = (float*)d_out;

    __half *Hh, *xh, *Wh, *xnh, *xheh;
    float* part;
    cudaGetSymbolAddress((void**)&Hh, g_Hh);
    cudaGetSymbolAddress((void**)&xh, g_xh);
    cudaGetSymbolAddress((void**)&Wh, g_Wh);
    cudaGetSymbolAddress((void**)&xnh, g_xnh);
    cudaGetSymbolAddress((void**)&xheh, g_xheh);
    cudaGetSymbolAddress((void**)&part, g_part);

    constexpr uint32_t SMEM_K1 = 4 * STAGE1;
    constexpr uint32_t SMEM_T  = 3 * ((uint32_t)(BK * PA_T) + BB);   // 104448
    constexpr uint32_t SMEM_F  = 3 * ((uint32_t)(128 * PA_F) + BB);  // 107520
    cudaFuncSetAttribute((const void*)gemm_k1,
                         cudaFuncAttributeMaxDynamicSharedMemorySize, SMEM_K1);
    cudaFuncSetAttribute((const void*)mma_gemm<true, false>,
                         cudaFuncAttributeMaxDynamicSharedMemorySize, SMEM_T);
    cudaFuncSetAttribute((const void*)mma_gemm<false, true>,
                         cudaFuncAttributeMaxDynamicSharedMemorySize, SMEM_F);

    // one-time streams + events
    static cudaStream_t sC = nullptr, s2 = nullptr, s3 = nullptr;
    static cudaEvent_t eFork = nullptr, eK1 = nullptr, eJ2 = nullptr, eJ3 = nullptr;
    static cudaEvent_t eC[K2_SPLIT] = {};
    static bool s_ok = false;
    if (!sC) {
        bool ok = (cudaStreamCreateWithFlags(&sC, cudaStreamNonBlocking) == cudaSuccess)
               && (cudaStreamCreateWithFlags(&s2, cudaStreamNonBlocking) == cudaSuccess)
               && (cudaStreamCreateWithFlags(&s3, cudaStreamNonBlocking) == cudaSuccess)
               && (cudaEventCreateWithFlags(&eFork, cudaEventDisableTiming) == cudaSuccess)
               && (cudaEventCreateWithFlags(&eK1, cudaEventDisableTiming) == cudaSuccess)
               && (cudaEventCreateWithFlags(&eJ2, cudaEventDisableTiming) == cudaSuccess)
               && (cudaEventCreateWithFlags(&eJ3, cudaEventDisableTiming) == cudaSuccess);
        for (int k = 0; k < K2_SPLIT && ok; ++k)
            ok = (cudaEventCreateWithFlags(&eC[k], cudaEventDisableTiming) == cudaSuccess);
        s_ok = ok;
    }

    const size_t chunkElems = (size_t)K2_LEN * N_EDGES;          // per H row-chunk
    const unsigned convBlocks = (unsigned)(chunkElems / 8 / 256);

    if (s_ok) {
        // fork convert stream: 6 H chunks, event after each
        cudaEventRecord(eFork, 0);
        cudaStreamWaitEvent(sC, eFork, 0);
        for (int k = 0; k < K2_SPLIT; ++k) {
            convert_H8<<<convBlocks, 256, 0, sC>>>(
                (const float4*)(H + (size_t)k * chunkElems),
                (uint4*)(Hh + (size_t)k * chunkElems));
            cudaEventRecord(eC[k], sC);
        }
    } else {
        convert_H8<<<(unsigned)((size_t)N_NODES * N_EDGES / 8 / 256), 256>>>(
            (const float4*)H, (uint4*)Hh);
    }

    // main: x+W convert, memset, K1
    {
        const size_t nx = (size_t)N_NODES * DIM / 4;
        const size_t nw = (size_t)DIM * DIM / 4;
        convert_xw<<<(unsigned)((nx + nw) / 256), 256>>>(
            (const float4*)x, (const float4*)W, (__half2*)xh, (__half2*)Wh);
    }
    cudaMemsetAsync(out, 0, (size_t)N_NODES * DIM * sizeof(float), 0);
    gemm_k1<<<dim3(2, N_NODES / 128, 1), 256, SMEM_K1>>>(
        xh, Wh, xnh, b, Dv, (size_t)N_NODES + 1);

    // K2: 6 z-slices, round-robin over {main, s2, s3}, each gated on its convert chunk
    const size_t plane = (size_t)N_EDGES * DIM;
    if (s_ok) {
        cudaEventRecord(eK1, 0);
        cudaStreamWaitEvent(s2, eK1, 0);
        cudaStreamWaitEvent(s3, eK1, 0);
        cudaStream_t zs[3] = {(cudaStream_t)0, s2, s3};
        for (int z = 0; z < K2_SPLIT; ++z) {
            cudaStream_t st = zs[z % 3];
            cudaStreamWaitEvent(st, eC[z], 0);
            mma_gemm<true, false><<<dim3(2, N_EDGES / 128, 1), 256, SMEM_T, st>>>(
                Hh, (size_t)N_EDGES, xnh, K2_LEN, z, part, plane, nullptr, 0);
        }
        cudaEventRecord(eJ2, s2);
        cudaEventRecord(eJ3, s3);
        cudaStreamWaitEvent(0, eJ2, 0);
        cudaStreamWaitEvent(0, eJ3, 0);
    } else {
        for (int z = 0; z < K2_SPLIT; ++z)
            mma_gemm<true, false><<<dim3(2, N_EDGES / 128, 1), 256, SMEM_T>>>(
                Hh, (size_t)N_EDGES, xnh, K2_LEN, z, part, plane, nullptr, 0);
    }

    // reduce + de-scale -> xhe fp16
    reduce_k2<<<(N_EDGES * DIM / 4) / 256, 256>>>(De);

    // K3: H @ xhe, split-K=3, fused dv-scale atomic epilogue -> out
    mma_gemm<false, true><<<dim3(2, N_NODES / 128, 3), 256, SMEM_F>>>(
        Hh, (size_t)N_EDGES, xheh, N_EDGES / 3, 0, out, 0,
        Dv, (size_t)N_NODES + 1);
}